// round 2
// baseline (speedup 1.0000x reference)
#include <cuda_runtime.h>
#include <cuda_fp16.h>
#include <cstdint>

// ============================================================================
// Problem sizes
// ============================================================================
#define TOKENS 8192
#define D_IN   4096
#define D_OUT  4096

// Scratch (device globals; no allocations allowed)
__device__ __half g_A[(size_t)TOKENS * D_IN];   // 64 MB: x in fp16
__device__ __half g_B[(size_t)D_OUT  * D_IN];   // 32 MB: W in fp16 (exact)

// ============================================================================
// GEMM configuration
// ============================================================================
constexpr int M_TILE = 128;
constexpr int N_TILE = 256;
constexpr int K_TILE = 64;                 // 64 fp16 = 128 B rows
constexpr int STAGES = 4;
constexpr int NUM_K  = D_IN / K_TILE;      // 64

constexpr int A_BYTES = M_TILE * 128;      // 16 KB
constexpr int B_BYTES = N_TILE * 128;      // 32 KB
constexpr int STAGE_BYTES = A_BYTES + B_BYTES;             // 48 KB
constexpr int SMEM_TOTAL  = STAGES * STAGE_BYTES;          // 192 KB

// ============================================================================
// Prep kernels: exact / rounded fp16 conversions
// ============================================================================
__global__ void prep_w_kernel(const int* __restrict__ wq) {
    const size_t total = (size_t)D_OUT * D_IN / 4;
    const size_t stride = (size_t)gridDim.x * blockDim.x;
    for (size_t i = (size_t)blockIdx.x * blockDim.x + threadIdx.x; i < total; i += stride) {
        int4 v = reinterpret_cast<const int4*>(wq)[i];
        __half2 p0 = __floats2half2_rn((float)v.x, (float)v.y);  // int8 exact in fp16
        __half2 p1 = __floats2half2_rn((float)v.z, (float)v.w);
        uint2 pk;
        pk.x = *reinterpret_cast<uint32_t*>(&p0);
        pk.y = *reinterpret_cast<uint32_t*>(&p1);
        *reinterpret_cast<uint2*>(&g_B[i * 4]) = pk;
    }
}

__global__ void prep_x_kernel(const float* __restrict__ x) {
    const size_t total = (size_t)TOKENS * D_IN / 4;
    const size_t stride = (size_t)gridDim.x * blockDim.x;
    for (size_t i = (size_t)blockIdx.x * blockDim.x + threadIdx.x; i < total; i += stride) {
        float4 v = reinterpret_cast<const float4*>(x)[i];
        __half2 p0 = __floats2half2_rn(v.x, v.y);
        __half2 p1 = __floats2half2_rn(v.z, v.w);
        uint2 pk;
        pk.x = *reinterpret_cast<uint32_t*>(&p0);
        pk.y = *reinterpret_cast<uint32_t*>(&p1);
        *reinterpret_cast<uint2*>(&g_A[i * 4]) = pk;
    }
}

// ============================================================================
// PTX helpers
// ============================================================================
__device__ __forceinline__ uint32_t smem_u32(const void* p) {
    uint32_t a;
    asm("{ .reg .u64 t; cvta.to.shared.u64 t, %1; cvt.u32.u64 %0, t; }"
        : "=r"(a) : "l"(p));
    return a;
}

__device__ __forceinline__ void cp_async16(uint32_t dst, const void* src) {
    asm volatile("cp.async.cg.shared.global [%0], [%1], 16;"
                 :: "r"(dst), "l"(src) : "memory");
}
__device__ __forceinline__ void cp_commit() {
    asm volatile("cp.async.commit_group;" ::: "memory");
}
__device__ __forceinline__ void cp_wait2() {
    asm volatile("cp.async.wait_group 2;" ::: "memory");
}

__device__ __forceinline__ void ldsm_x4(uint32_t& r0, uint32_t& r1,
                                        uint32_t& r2, uint32_t& r3, uint32_t addr) {
    asm volatile("ldmatrix.sync.aligned.m8n8.x4.shared.b16 {%0,%1,%2,%3}, [%4];"
                 : "=r"(r0), "=r"(r1), "=r"(r2), "=r"(r3) : "r"(addr));
}

__device__ __forceinline__ void mma16816(float* c, const uint32_t* a, const uint32_t* b) {
    asm volatile(
        "mma.sync.aligned.m16n8k16.row.col.f32.f16.f16.f32 "
        "{%0,%1,%2,%3}, {%4,%5,%6,%7}, {%8,%9}, {%0,%1,%2,%3};"
        : "+f"(c[0]), "+f"(c[1]), "+f"(c[2]), "+f"(c[3])
        : "r"(a[0]), "r"(a[1]), "r"(a[2]), "r"(a[3]), "r"(b[0]), "r"(b[1]));
}

// ============================================================================
// GEMM: out[M,N] = A[M,K] * B[N,K]^T * scale[n] + bias[n]
//   CTA 128x256x64, 512 threads (16 warps, 2m x 8n), warp tile 64x32
// ============================================================================
__global__ void __launch_bounds__(512, 1) gemm_kernel(
    const float* __restrict__ scales,
    const float* __restrict__ bias,
    float* __restrict__ out)
{
    extern __shared__ char smem[];
    const uint32_t sb = smem_u32(smem);
    const int tid = threadIdx.x;
    const int wid = tid >> 5;
    const int lane = tid & 31;
    const int wm = wid >> 3;       // 0..1
    const int wn = wid & 7;        // 0..7

    // CTA swizzle for L2 reuse
    constexpr int TILES_N = D_OUT / N_TILE;   // 16
    constexpr int GROUP = 8;
    const int bid = blockIdx.x;
    const int r = bid % (GROUP * TILES_N);
    const int tile_m = (bid / (GROUP * TILES_N)) * GROUP + (r % GROUP);
    const int tile_n = r / GROUP;
    const int row0 = tile_m * M_TILE;
    const int col0 = tile_n * N_TILE;

    const __half* gA = g_A;
    const __half* gB = g_B;

    // ---- load issue helper (all 512 threads) ----
    // A: 1024 16B-chunks (row = c>>3, c16 = c&7); B: 2048 chunks
    auto issue_stage = [&](int kc, int stage) {
        const int kbase = kc * K_TILE;
        const uint32_t sA = sb + stage * STAGE_BYTES;
        const uint32_t sB = sA + A_BYTES;
        #pragma unroll
        for (int j = 0; j < 2; j++) {
            int ch = tid + j * 512;
            int row = ch >> 3, c16 = ch & 7;
            const __half* src = gA + (size_t)(row0 + row) * D_IN + kbase + c16 * 8;
            uint32_t dst = sA + row * 128 + ((c16 * 16) ^ ((row & 7) << 4));
            cp_async16(dst, src);
        }
        #pragma unroll
        for (int j = 0; j < 4; j++) {
            int ch = tid + j * 512;
            int row = ch >> 3, c16 = ch & 7;
            const __half* src = gB + (size_t)(col0 + row) * D_IN + kbase + c16 * 8;
            uint32_t dst = sB + row * 128 + ((c16 * 16) ^ ((row & 7) << 4));
            cp_async16(dst, src);
        }
    };

    // ---- prologue: fill STAGES-1 stages ----
    #pragma unroll
    for (int s = 0; s < STAGES - 1; s++) {
        issue_stage(s, s);
        cp_commit();
    }

    // ---- per-thread ldmatrix base addresses ----
    // swizzle: off = row*128 + kbyte; sw = off ^ ((row&7)<<4); row&7 == lane&7
    const uint32_t xm   = (lane & 7) << 4;     // bits 4..6
    const uint32_t xm_hi = xm & 0x60;          // affects ks*32 part
    const uint32_t xm_lo = xm & 0x10;          // affects 16B col part

    // A: rowA = wm*64 + m*16 + (lane&15); colpart = ((lane>>4)<<4) bytes
    uint32_t aBase[4];
    {
        uint32_t colp = ((uint32_t)(lane >> 4) << 4) ^ xm_lo;
        #pragma unroll
        for (int m = 0; m < 4; m++)
            aBase[m] = (uint32_t)((wm * 64 + m * 16 + (lane & 15)) * 128) + colp;
    }
    // B: rowB = wn*32 + ch*16 + ((lane>>4)<<3) + (lane&7); colpart = ((lane>>3)&1)<<4
    uint32_t bBase[2];
    {
        uint32_t colp = (((uint32_t)(lane >> 3) & 1) << 4) ^ xm_lo;
        uint32_t rowB = (uint32_t)(wn * 32 + ((lane >> 4) << 3) + (lane & 7));
        #pragma unroll
        for (int ch = 0; ch < 2; ch++)
            bBase[ch] = (rowB + ch * 16) * 128 + colp;
    }

    float acc[4][4][4];
    #pragma unroll
    for (int m = 0; m < 4; m++)
        #pragma unroll
        for (int n = 0; n < 4; n++)
            #pragma unroll
            for (int v = 0; v < 4; v++) acc[m][n][v] = 0.0f;

    // ---- main loop ----
    for (int kc = 0; kc < NUM_K; kc++) {
        cp_wait2();
        __syncthreads();

        // issue next stage (buffer freed by compute of kc-1, fenced by the sync)
        if (kc + STAGES - 1 < NUM_K)
            issue_stage(kc + STAGES - 1, (kc + STAGES - 1) % STAGES);
        cp_commit();

        const uint32_t sA = sb + (kc % STAGES) * STAGE_BYTES;
        const uint32_t sBb = sA + A_BYTES;

        #pragma unroll
        for (int ks = 0; ks < 4; ks++) {
            const uint32_t kofs = ((uint32_t)(ks * 32)) ^ xm_hi;
            uint32_t a[4][4];
            #pragma unroll
            for (int m = 0; m < 4; m++)
                ldsm_x4(a[m][0], a[m][1], a[m][2], a[m][3], sA + aBase[m] + kofs);
            uint32_t b[4][2];
            #pragma unroll
            for (int ch = 0; ch < 2; ch++) {
                uint32_t r0, r1, r2, r3;
                ldsm_x4(r0, r1, r2, r3, sBb + bBase[ch] + kofs);
                b[ch * 2 + 0][0] = r0; b[ch * 2 + 0][1] = r1;
                b[ch * 2 + 1][0] = r2; b[ch * 2 + 1][1] = r3;
            }
            #pragma unroll
            for (int m = 0; m < 4; m++)
                #pragma unroll
                for (int n = 0; n < 4; n++)
                    mma16816(acc[m][n], a[m], b[n]);
        }
        __syncthreads();
    }

    // ---- epilogue: acc * scale[col] + bias[col] ----
    // c layout: c0,c1 -> (row lane/4, col 2*(lane%4)+{0,1}); c2,c3 -> row+8
    const int cbase = col0 + wn * 32 + (lane & 3) * 2;
    float2 sc[4], bi[4];
    #pragma unroll
    for (int n = 0; n < 4; n++) {
        sc[n] = __ldg(reinterpret_cast<const float2*>(scales + cbase + n * 8));
        bi[n] = __ldg(reinterpret_cast<const float2*>(bias   + cbase + n * 8));
    }
    const int rbase = row0 + wm * 64 + (lane >> 2);
    #pragma unroll
    for (int m = 0; m < 4; m++) {
        #pragma unroll
        for (int n = 0; n < 4; n++) {
            const size_t o0 = (size_t)(rbase + m * 16) * D_OUT + cbase + n * 8;
            const size_t o1 = o0 + 8 * D_OUT;
            float2 v0, v1;
            v0.x = fmaf(acc[m][n][0], sc[n].x, bi[n].x);
            v0.y = fmaf(acc[m][n][1], sc[n].y, bi[n].y);
            v1.x = fmaf(acc[m][n][2], sc[n].x, bi[n].x);
            v1.y = fmaf(acc[m][n][3], sc[n].y, bi[n].y);
            *reinterpret_cast<float2*>(out + o0) = v0;
            *reinterpret_cast<float2*>(out + o1) = v1;
        }
    }
}

// ============================================================================
// Host
// ============================================================================
extern "C" void kernel_launch(void* const* d_in, const int* in_sizes, int n_in,
                              void* d_out, int out_size)
{
    const float* x  = (const float*)d_in[0];
    const int*   wq = (const int*)  d_in[1];
    const float* sc = (const float*)d_in[2];
    const float* bi = (const float*)d_in[3];
    float* out = (float*)d_out;

    prep_w_kernel<<<2048, 256>>>(wq);
    prep_x_kernel<<<4096, 256>>>(x);

    static bool attr_set = false;
    // (setting an attribute is idempotent and not a work-guard; safe every call)
    cudaFuncSetAttribute(gemm_kernel, cudaFuncAttributeMaxDynamicSharedMemorySize,
                         SMEM_TOTAL);
    (void)attr_set;

    const int grid = (TOKENS / M_TILE) * (D_OUT / N_TILE);  // 64 * 16 = 1024
    gemm_kernel<<<grid, 512, SMEM_TOTAL>>>(sc, bi, out);
}